// round 1
// baseline (speedup 1.0000x reference)
#include <cuda_runtime.h>
#include <cuda_bf16.h>

#define TT 2048
#define CC 64
#define EE 16
#define TB 16            // t-rows per block
#define NTHREADS (TB*EE) // 256
#define EPSF 1e-6f

__device__ __forceinline__ float logit_clipped(float x, float omx) {
    // reference: x clipped to [eps, 1-eps]; logit = log(x) - log(1-x)
    if (x < EPSF)        { x = EPSF;        omx = 1.0f - EPSF; }
    else if (omx < EPSF) { omx = EPSF;      x   = 1.0f - EPSF; }
    return __logf(x) - __logf(omx);
}

__global__ __launch_bounds__(NTHREADS)
void role_learner_kernel(const float* __restrict__ pbar,
                         const float* __restrict__ rho_dir,
                         const float* __restrict__ rho_ind,
                         const float* __restrict__ gamma_dir,
                         const float* __restrict__ gamma_ind,
                         const float* __restrict__ gamma_ctr,
                         const float* __restrict__ bias,
                         float* __restrict__ out)
{
    __shared__ float sp [TB * CC];   // p tile      [TB][C]
    __shared__ float srd[CC * EE];   // rho_dir     [C][E]
    __shared__ float sri[CC * EE];   // rho_ind     [C][E]

    const int tid = threadIdx.x;
    const int t0  = blockIdx.x * TB;

    #pragma unroll
    for (int i = tid; i < TB * CC; i += NTHREADS)
        sp[i] = pbar[t0 * CC + i];
    #pragma unroll
    for (int i = tid; i < CC * EE; i += NTHREADS) {
        srd[i] = fminf(fmaxf(rho_dir[i], 0.0f), 1.0f);
        sri[i] = fminf(fmaxf(rho_ind[i], 0.0f), 1.0f);
    }
    __syncthreads();

    const int e  = tid & (EE - 1);
    const int tl = tid >> 4;
    const float* prow = &sp[tl * CC];

    // S[k-1] = sum_c a_c^k  for k = 1..16
    float S[16];
    #pragma unroll
    for (int k = 0; k < 16; k++) S[k] = 0.0f;
    float LD = 0.0f;   // sum_c log(max(1 - p*rd, eps))

    #pragma unroll 4
    for (int c = 0; c < CC; c++) {
        const float p  = prow[c];
        const float rd = srd[c * EE + e];
        LD += __logf(fmaxf(fmaf(-p, rd, 1.0f), EPSF));

        const float a  = p * sri[c * EE + e];
        const float a2 = a * a;
        float o  = a;   S[0] += o;    // odd powers  a^1, a^3, ...
        float ev = a2;  S[1] += ev;   // even powers a^2, a^4, ...
        #pragma unroll
        for (int k = 1; k < 8; k++) {
            o  *= a2;  S[2*k]     += o;    // a^(2k+1)
            ev *= a2;  S[2*k + 1] += ev;   // a^(2k+2)
        }
    }

    // Z = 0.5*(log_all - log_diag) = sum_{i<j} log(1 - a_i a_j)
    //   = -0.5 * sum_{k=1..8} (S_k^2 - S_{2k}) / k     (series, a < 0.5)
    const float coef[8] = { -0.5f/1.0f, -0.5f/2.0f, -0.5f/3.0f, -0.5f/4.0f,
                            -0.5f/5.0f, -0.5f/6.0f, -0.5f/7.0f, -0.5f/8.0f };
    float Z = 0.0f;
    #pragma unroll
    for (int k = 1; k <= 8; k++)
        Z += coef[k-1] * (S[k-1] * S[k-1] - S[2*k - 1]);

    const float eD = __expf(LD);   // 1 - D (exact complement)
    const float eI = __expf(Z);    // 1 - I
    const float D  = 1.0f - eD;
    const float I  = 1.0f - eI;

    const float ctr    = eD * eI;                  // (1-D)(1-I)
    const float om_ctr = fmaf(-eD, eI, 1.0f);      // 1 - ctr, single rounding

    const float lD = logit_clipped(D,   eD);
    const float lI = logit_clipped(I,   eI);
    const float lC = logit_clipped(ctr, om_ctr);

    const float logits = gamma_dir[e] * lD + gamma_ind[e] * lI
                       + gamma_ctr[e] * lC + bias[e];
    out[(t0 + tl) * EE + e] = 1.0f / (1.0f + __expf(-logits));
}

extern "C" void kernel_launch(void* const* d_in, const int* in_sizes, int n_in,
                              void* d_out, int out_size)
{
    (void)in_sizes; (void)n_in; (void)out_size;
    const float* pbar      = (const float*)d_in[0];
    const float* rho_dir   = (const float*)d_in[1];
    const float* rho_ind   = (const float*)d_in[2];
    // d_in[3] = rho_ctr (unused in forward)
    const float* gamma_dir = (const float*)d_in[4];
    const float* gamma_ind = (const float*)d_in[5];
    const float* gamma_ctr = (const float*)d_in[6];
    const float* bias      = (const float*)d_in[7];
    float* out = (float*)d_out;

    role_learner_kernel<<<TT / TB, NTHREADS>>>(
        pbar, rho_dir, rho_ind, gamma_dir, gamma_ind, gamma_ctr, bias, out);
}

// round 2
// speedup vs baseline: 1.0239x; 1.0239x over previous
#include <cuda_runtime.h>
#include <cuda_bf16.h>

#define TT 2048
#define CC 64
#define EE 16
#define TB 4              // t-rows per block
#define NPART 4           // c-loop split factor (partner threads per output)
#define NTHREADS (TB*EE*NPART) // 256
#define EPSF 1e-6f

__device__ __forceinline__ float logit_clipped(float x, float omx) {
    // reference: x clipped to [eps, 1-eps]; logit = log(x) - log(1-x)
    if (x < EPSF)        { x = EPSF;   omx = 1.0f - EPSF; }
    else if (omx < EPSF) { omx = EPSF; x   = 1.0f - EPSF; }
    return __logf(x) - __logf(omx);
}

#define RED4(v)  v += __shfl_xor_sync(0xffffffffu, v, 1); \
                 v += __shfl_xor_sync(0xffffffffu, v, 2);

__global__ __launch_bounds__(NTHREADS)
void role_learner_kernel(const float* __restrict__ pbar,
                         const float* __restrict__ rho_dir,
                         const float* __restrict__ rho_ind,
                         const float* __restrict__ gamma_dir,
                         const float* __restrict__ gamma_ind,
                         const float* __restrict__ gamma_ctr,
                         const float* __restrict__ bias,
                         float* __restrict__ out)
{
    __shared__ float sp [TB * CC];   // p tile   [TB][C]
    __shared__ float srd[CC * EE];   // rho_dir  [C][E], clipped
    __shared__ float sri[CC * EE];   // rho_ind  [C][E], clipped

    const int tid = threadIdx.x;
    const int t0  = blockIdx.x * TB;

    #pragma unroll
    for (int i = tid; i < TB * CC; i += NTHREADS)
        sp[i] = pbar[t0 * CC + i];
    #pragma unroll
    for (int i = tid; i < CC * EE; i += NTHREADS) {
        srd[i] = fminf(fmaxf(rho_dir[i], 0.0f), 1.0f);
        sri[i] = fminf(fmaxf(rho_ind[i], 0.0f), 1.0f);
    }
    __syncthreads();

    // tid bits: [1:0]=part, [5:2]=e, [7:6]=tl  -> partners adjacent in lane bits 0-1
    const int part = tid & 3;
    const int e    = (tid >> 2) & (EE - 1);
    const int tl   = tid >> 6;
    const float* prow = &sp[tl * CC];

    // Partial moments S_k = sum_c a_c^k (k=1..8) over this part's 16 c's,
    // and the running product of direct-terms (one log at the end).
    float S1 = 0.f, S2 = 0.f, S3 = 0.f, S4 = 0.f;
    float S5 = 0.f, S6 = 0.f, S7 = 0.f, S8 = 0.f;
    float prod = 1.0f;

    #pragma unroll
    for (int j = 0; j < CC / NPART; j++) {
        const int c  = part + NPART * j;       // stride-4 interleave: bank-friendly
        const float p  = prow[c];
        const float rd = srd[c * EE + e];
        const float ri = sri[c * EE + e];

        prod *= fmaxf(fmaf(-p, rd, 1.0f), EPSF);

        const float a  = p * ri;
        const float a2 = a * a;
        const float a3 = a2 * a;
        const float a4 = a2 * a2;
        const float a5 = a4 * a;
        const float a6 = a4 * a2;
        const float a7 = a4 * a3;
        const float a8 = a4 * a4;
        S1 += a;  S2 += a2; S3 += a3; S4 += a4;
        S5 += a5; S6 += a6; S7 += a7; S8 += a8;
    }

    float LD = __logf(prod);   // = sum_c log(max(1 - p*rd, eps)) for this part

    // Butterfly-reduce the 4 partners (lane bits 0-1)
    RED4(LD);
    RED4(S1); RED4(S2); RED4(S3); RED4(S4);
    RED4(S5); RED4(S6); RED4(S7); RED4(S8);

    // Z = sum_{i<j} log(1 - a_i a_j) = -0.5 * sum_{k>=1} (S_k^2 - S_{2k})/k, k<=4
    const float Z = -0.5f * ( (S1*S1 - S2)
                    + 0.5f       * (S2*S2 - S4)
                    + 0.3333333433f * (S3*S3 - S6)
                    + 0.25f      * (S4*S4 - S8) );

    const float eD = __expf(LD);   // 1 - D (exact complement)
    const float eI = __expf(Z);    // 1 - I
    const float D  = 1.0f - eD;
    const float I  = 1.0f - eI;

    const float ctr    = eD * eI;                 // (1-D)(1-I)
    const float om_ctr = fmaf(-eD, eI, 1.0f);     // 1 - ctr

    const float lD = logit_clipped(D,   eD);
    const float lI = logit_clipped(I,   eI);
    const float lC = logit_clipped(ctr, om_ctr);

    const float logits = gamma_dir[e] * lD + gamma_ind[e] * lI
                       + gamma_ctr[e] * lC + bias[e];

    if (part == 0)
        out[(t0 + tl) * EE + e] = 1.0f / (1.0f + __expf(-logits));
}

extern "C" void kernel_launch(void* const* d_in, const int* in_sizes, int n_in,
                              void* d_out, int out_size)
{
    (void)in_sizes; (void)n_in; (void)out_size;
    const float* pbar      = (const float*)d_in[0];
    const float* rho_dir   = (const float*)d_in[1];
    const float* rho_ind   = (const float*)d_in[2];
    // d_in[3] = rho_ctr (unused in forward)
    const float* gamma_dir = (const float*)d_in[4];
    const float* gamma_ind = (const float*)d_in[5];
    const float* gamma_ctr = (const float*)d_in[6];
    const float* bias      = (const float*)d_in[7];
    float* out = (float*)d_out;

    role_learner_kernel<<<TT / TB, NTHREADS>>>(
        pbar, rho_dir, rho_ind, gamma_dir, gamma_ind, gamma_ctr, bias, out);
}

// round 3
// speedup vs baseline: 1.1525x; 1.1256x over previous
#include <cuda_runtime.h>
#include <cuda_bf16.h>

#define TT 2048
#define CC 64
#define EE 16
#define TB 4                      // t-rows per block
#define NPART 2                   // c-split; partner = lane xor 16
#define NTHREADS (TB*EE*NPART)    // 128
#define EPSF 1e-6f

__device__ __forceinline__ float logit_clipped(float x, float omx) {
    // reference: x clipped to [eps, 1-eps]; logit = log(x) - log(1-x)
    if (x < EPSF)        { x = EPSF;   omx = 1.0f - EPSF; }
    else if (omx < EPSF) { omx = EPSF; x   = 1.0f - EPSF; }
    return __logf(x) - __logf(omx);
}

#define RED2(v) v += __shfl_xor_sync(0xffffffffu, v, 16);

__global__ __launch_bounds__(NTHREADS)
void role_learner_kernel(const float* __restrict__ pbar,
                         const float* __restrict__ rho_dir,
                         const float* __restrict__ rho_ind,
                         const float* __restrict__ gamma_dir,
                         const float* __restrict__ gamma_ind,
                         const float* __restrict__ gamma_ctr,
                         const float* __restrict__ bias,
                         float* __restrict__ out)
{
    __shared__ float sp [TB * CC];   // p tile   [TB][C]
    __shared__ float srd[CC * EE];   // rho_dir  [C][E], clipped
    __shared__ float sri[CC * EE];   // rho_ind  [C][E], clipped

    const int tid = threadIdx.x;
    const int t0  = blockIdx.x * TB;

    #pragma unroll
    for (int i = tid; i < TB * CC; i += NTHREADS)
        sp[i] = pbar[t0 * CC + i];
    #pragma unroll
    for (int i = tid; i < CC * EE; i += NTHREADS) {
        srd[i] = fminf(fmaxf(rho_dir[i], 0.0f), 1.0f);
        sri[i] = fminf(fmaxf(rho_ind[i], 0.0f), 1.0f);
    }
    __syncthreads();

    // lane bits: [3:0]=e, [4]=part  -> warp covers 16 e x 2 parts (conflict-free),
    // [6:5]=tl (t-row within block)
    const int e    = tid & (EE - 1);
    const int part = (tid >> 4) & 1;
    const int tl   = tid >> 5;
    const float* prow = &sp[tl * CC];

    // Moments S_k = sum_c a^k (k=1..8) over this part's 32 c's; product of
    // direct terms (single log at the end).
    float S1 = 0.f, S2 = 0.f, S3 = 0.f, S4 = 0.f;
    float S5 = 0.f, S6 = 0.f, S7 = 0.f, S8 = 0.f;
    float prod = 1.0f;

    #pragma unroll
    for (int j = 0; j < CC / NPART; j++) {
        const int c  = 2 * j + part;
        const float p  = prow[c];
        const float rd = srd[c * EE + e];   // bank = (16*part + e) % 32: conflict-free
        const float ri = sri[c * EE + e];

        prod *= fmaxf(fmaf(-p, rd, 1.0f), EPSF);

        const float a  = p * ri;
        const float a2 = a  * a;
        const float a3 = a2 * a;
        const float a4 = a2 * a2;
        S1 += a;  S2 += a2;  S3 += a3;  S4 += a4;
        S5 = fmaf(a4, a,  S5);
        S6 = fmaf(a4, a2, S6);
        S7 = fmaf(a4, a3, S7);
        S8 = fmaf(a4, a4, S8);
    }

    float LD = __logf(prod);   // partial sum_c log(max(1 - p*rd, eps))

    // single butterfly round: partner differs in lane bit 4 (part)
    RED2(LD);
    RED2(S1); RED2(S2); RED2(S3); RED2(S4);
    RED2(S5); RED2(S6); RED2(S7); RED2(S8);

    // Z = sum_{i<j} log(1 - a_i a_j) = -0.5 * sum_{k=1..4} (S_k^2 - S_{2k}) / k
    const float Z = -0.5f * ( (S1*S1 - S2)
                    + 0.5f          * (S2*S2 - S4)
                    + 0.3333333433f * (S3*S3 - S6)
                    + 0.25f         * (S4*S4 - S8) );

    const float eD = __expf(LD);   // 1 - D (exact complement)
    const float eI = __expf(Z);    // 1 - I
    const float D  = 1.0f - eD;
    const float I  = 1.0f - eI;

    const float ctr    = eD * eI;                 // (1-D)(1-I)
    const float om_ctr = fmaf(-eD, eI, 1.0f);     // 1 - ctr

    const float lD = logit_clipped(D,   eD);
    const float lI = logit_clipped(I,   eI);
    const float lC = logit_clipped(ctr, om_ctr);

    const float logits = gamma_dir[e] * lD + gamma_ind[e] * lI
                       + gamma_ctr[e] * lC + bias[e];

    if (part == 0)
        out[(t0 + tl) * EE + e] = 1.0f / (1.0f + __expf(-logits));
}

extern "C" void kernel_launch(void* const* d_in, const int* in_sizes, int n_in,
                              void* d_out, int out_size)
{
    (void)in_sizes; (void)n_in; (void)out_size;
    const float* pbar      = (const float*)d_in[0];
    const float* rho_dir   = (const float*)d_in[1];
    const float* rho_ind   = (const float*)d_in[2];
    // d_in[3] = rho_ctr (unused in forward)
    const float* gamma_dir = (const float*)d_in[4];
    const float* gamma_ind = (const float*)d_in[5];
    const float* gamma_ctr = (const float*)d_in[6];
    const float* bias      = (const float*)d_in[7];
    float* out = (float*)d_out;

    role_learner_kernel<<<TT / TB, NTHREADS>>>(
        pbar, rho_dir, rho_ind, gamma_dir, gamma_ind, gamma_ctr, bias, out);
}